// round 5
// baseline (speedup 1.0000x reference)
#include <cuda_runtime.h>
#include <cuda_fp16.h>

#define N_B    4
#define C_IN   256
#define T_LEN  2048
#define HEADS  8
#define DK     32

// Scratch: q (pre-scaled, tf32-rounded bits), k (tf32-rounded bits), v (fp16).
// Layout [N][256][T] (== [N][H][d][T]).
__device__ float  g_q[N_B * C_IN * T_LEN];
__device__ float  g_k[N_B * C_IN * T_LEN];
__device__ __half g_v[N_B * C_IN * T_LEN];

__device__ __forceinline__ unsigned f2tf32(float f) {
    unsigned u;
    asm("cvt.rna.tf32.f32 %0, %1;" : "=r"(u) : "f"(f));
    return u;
}
__device__ __forceinline__ float ex2(float x) {
    float y;
    asm("ex2.approx.f32 %0, %1;" : "=f"(y) : "f"(x));
    return y;
}
__device__ __forceinline__ void mma_tf32(float d[4], const unsigned a[4],
                                         unsigned b0, unsigned b1) {
    asm volatile(
        "mma.sync.aligned.m16n8k8.row.col.f32.tf32.tf32.f32 "
        "{%0,%1,%2,%3}, {%4,%5,%6,%7}, {%8,%9}, {%0,%1,%2,%3};"
        : "+f"(d[0]), "+f"(d[1]), "+f"(d[2]), "+f"(d[3])
        : "r"(a[0]), "r"(a[1]), "r"(a[2]), "r"(a[3]), "r"(b0), "r"(b1));
}
__device__ __forceinline__ void mma_f16(float d[4], const unsigned a[4],
                                        unsigned b0, unsigned b1) {
    asm volatile(
        "mma.sync.aligned.m16n8k16.row.col.f32.f16.f16.f32 "
        "{%0,%1,%2,%3}, {%4,%5,%6,%7}, {%8,%9}, {%0,%1,%2,%3};"
        : "+f"(d[0]), "+f"(d[1]), "+f"(d[2]), "+f"(d[3])
        : "r"(a[0]), "r"(a[1]), "r"(a[2]), "r"(a[3]), "r"(b0), "r"(b1));
}
__device__ __forceinline__ void ldsm4(unsigned r[4], unsigned addr) {
    asm volatile(
        "ldmatrix.sync.aligned.m8n8.x4.shared.b16 {%0,%1,%2,%3}, [%4];"
        : "=r"(r[0]), "=r"(r[1]), "=r"(r[2]), "=r"(r[3]) : "r"(addr));
}
__device__ __forceinline__ unsigned pack_h2(float x, float y) {
    __half2 h = __floats2half2_rn(x, y);
    return *(unsigned*)&h;
}
__device__ __forceinline__ unsigned su32(const void* p) {
    return (unsigned)__cvta_generic_to_shared(p);
}

// ---------------------------------------------------------------------------
// Projection + format conversion.
//   wsel 0 (q): acc * (1/sqrt(dk) * log2e), tf32-rounded bits.
//   wsel 1 (k): tf32-rounded bits.
//   wsel 2 (v): fp16.
// ---------------------------------------------------------------------------
__global__ __launch_bounds__(256) void proj_kernel(
    const float* __restrict__ x,
    const float* __restrict__ Wq,
    const float* __restrict__ Wk,
    const float* __restrict__ Wv)
{
    __shared__ float Ws[32][65];
    __shared__ float Xs[32][64];

    const int tid = threadIdx.x;
    const int tx  = tid & 15;
    const int ty  = tid >> 4;
    const int t0  = blockIdx.x * 64;
    const int by  = blockIdx.y;
    const int n   = blockIdx.z;
    const int wsel = by >> 2;
    const int o0   = (by & 3) * 64;

    const float* W  = (wsel == 0) ? Wq : (wsel == 1) ? Wk : Wv;
    const float* xb = x + (size_t)n * C_IN * T_LEN;

    float acc[4][4];
    #pragma unroll
    for (int i = 0; i < 4; i++)
        #pragma unroll
        for (int j = 0; j < 4; j++) acc[i][j] = 0.0f;

    for (int c0 = 0; c0 < C_IN; c0 += 32) {
        #pragma unroll
        for (int l = 0; l < 8; l++) {
            int e = l * 256 + tid;
            int o = e >> 5;
            int c = e & 31;
            Ws[c][o] = W[(o0 + o) * C_IN + c0 + c];
        }
        #pragma unroll
        for (int l = 0; l < 8; l++) {
            int e = l * 256 + tid;
            int c = e >> 6;
            int t = e & 63;
            Xs[c][t] = xb[(size_t)(c0 + c) * T_LEN + t0 + t];
        }
        __syncthreads();

        #pragma unroll
        for (int c = 0; c < 32; c++) {
            float wf[4];
            #pragma unroll
            for (int i = 0; i < 4; i++) wf[i] = Ws[c][ty * 4 + i];
            float4 xv = *(const float4*)&Xs[c][tx * 4];
            float xf[4] = {xv.x, xv.y, xv.z, xv.w};
            #pragma unroll
            for (int i = 0; i < 4; i++)
                #pragma unroll
                for (int j = 0; j < 4; j++)
                    acc[i][j] = fmaf(wf[i], xf[j], acc[i][j]);
        }
        __syncthreads();
    }

    const float QS = 0.17677669529663689f * 1.4426950408889634f;

    if (wsel == 0) {
        float* ob = g_q + (size_t)n * C_IN * T_LEN;
        #pragma unroll
        for (int i = 0; i < 4; i++) {
            float4 v = make_float4(
                __uint_as_float(f2tf32(acc[i][0] * QS)),
                __uint_as_float(f2tf32(acc[i][1] * QS)),
                __uint_as_float(f2tf32(acc[i][2] * QS)),
                __uint_as_float(f2tf32(acc[i][3] * QS)));
            *(float4*)&ob[(size_t)(o0 + ty * 4 + i) * T_LEN + t0 + tx * 4] = v;
        }
    } else if (wsel == 1) {
        float* ob = g_k + (size_t)n * C_IN * T_LEN;
        #pragma unroll
        for (int i = 0; i < 4; i++) {
            float4 v = make_float4(
                __uint_as_float(f2tf32(acc[i][0])),
                __uint_as_float(f2tf32(acc[i][1])),
                __uint_as_float(f2tf32(acc[i][2])),
                __uint_as_float(f2tf32(acc[i][3])));
            *(float4*)&ob[(size_t)(o0 + ty * 4 + i) * T_LEN + t0 + tx * 4] = v;
        }
    } else {
        __half* ob = g_v + (size_t)n * C_IN * T_LEN;
        #pragma unroll
        for (int i = 0; i < 4; i++) {
            uint2 v;
            v.x = pack_h2(acc[i][0], acc[i][1]);
            v.y = pack_h2(acc[i][2], acc[i][3]);
            *(uint2*)&ob[(size_t)(o0 + ty * 4 + i) * T_LEN + t0 + tx * 4] = v;
        }
    }
}

// ---------------------------------------------------------------------------
// Tensor-core flash attention, ldmatrix edition.
//   CTA: 64 queries, 4 warps. K-tile = 64 keys.
//   K smem: 64 blocks (8 kq-groups x 8 j) of 8x16B rows, 144B stride.
//     block (kk*2+h)*8+j, row = key%8 (n), word = k%4. ldmatrix.x4 yields
//     tf32 B-frags directly.
//   V smem: 32 blocks (8 kp-groups x 4 jn), row = dv%8, word = keypair.
// grid = (T/64, H, N), block = 128.
// ---------------------------------------------------------------------------
#define QT 64
#define KT 64

__global__ __launch_bounds__(128) void attn_kernel(float* __restrict__ out)
{
    __shared__ __align__(16) unsigned char Kb[64 * 144];
    __shared__ __align__(16) unsigned char Vb[32 * 144];
    __shared__ float Qs[64][33];

    const int tid  = threadIdx.x;
    const int warp = tid >> 5;
    const int lane = tid & 31;
    const int g    = lane >> 2;
    const int c    = lane & 3;

    const int t0 = blockIdx.x * QT;
    const int h  = blockIdx.y;
    const int n  = blockIdx.z;

    const size_t base = ((size_t)n * HEADS + h) * DK * T_LEN;
    const float*  qb = g_q + base;
    const float*  kb = g_k + base;
    const __half* vb = g_v + base;

    // Stage Q (already scaled + tf32 bits) transposed to [q][d].
    for (int i = tid; i < QT * DK / 4; i += 128) {
        int d  = i >> 4;
        int q4 = (i & 15) * 4;
        float4 v = *(const float4*)&qb[(size_t)d * T_LEN + t0 + q4];
        Qs[q4 + 0][d] = v.x; Qs[q4 + 1][d] = v.y;
        Qs[q4 + 2][d] = v.z; Qs[q4 + 3][d] = v.w;
    }
    __syncthreads();

    const int q0 = warp * 16;
    unsigned aq[4][4];
    #pragma unroll
    for (int kk = 0; kk < 4; kk++) {
        aq[kk][0] = __float_as_uint(Qs[q0 + g    ][kk * 8 + c    ]);
        aq[kk][1] = __float_as_uint(Qs[q0 + g + 8][kk * 8 + c    ]);
        aq[kk][2] = __float_as_uint(Qs[q0 + g    ][kk * 8 + c + 4]);
        aq[kk][3] = __float_as_uint(Qs[q0 + g + 8][kk * 8 + c + 4]);
    }

    const unsigned KsB = su32(Kb);
    const unsigned VsB = su32(Vb);
    // ldmatrix lane addresses (lane>>3 selects block within the x4 group).
    const unsigned ka = KsB + (unsigned)((lane >> 3) * 8 * 144 + (lane & 7) * 16);
    const unsigned va = VsB + (unsigned)((lane >> 3) * 4 * 144 + (lane & 7) * 16);

    float O[4][4];
    #pragma unroll
    for (int jn = 0; jn < 4; jn++)
        #pragma unroll
        for (int i = 0; i < 4; i++) O[jn][i] = 0.0f;
    float m0 = -1e30f, m1 = -1e30f, l0 = 0.0f, l1 = 0.0f;

    for (int s0 = 0; s0 < T_LEN; s0 += KT) {
        __syncthreads();
        // Stage K: 32 d x 64 keys words -> ldmatrix blocks (pure copy).
        for (int i = tid; i < 512; i += 128) {
            int d  = i >> 4;           // 0..31
            int k4 = i & 15;           // key/4
            float4 kv = *(const float4*)&kb[(size_t)d * T_LEN + s0 + k4 * 4];
            int kk = d >> 3, cc = d & 7;
            int hh = cc >> 2, w = cc & 3;
            int j = k4 >> 1, g0 = (k4 & 1) * 4;
            unsigned char* p = Kb + ((kk * 2 + hh) * 8 + j) * 144 + g0 * 16 + w * 4;
            *(float*)(p     ) = kv.x;
            *(float*)(p + 16) = kv.y;
            *(float*)(p + 32) = kv.z;
            *(float*)(p + 48) = kv.w;
        }
        // Stage V: 32 dv x 64 keys halves -> ldmatrix blocks (uint4 copy).
        for (int i = tid; i < 256; i += 128) {
            int dv = i >> 3;           // 0..31
            int k8 = i & 7;            // key/8
            uint4 vv = *(const uint4*)&vb[(size_t)dv * T_LEN + s0 + k8 * 8];
            int jn = dv >> 3, row = dv & 7;
            int jp = k8 >> 1, hh = k8 & 1;
            *(uint4*)(Vb + ((jp * 2 + hh) * 4 + jn) * 144 + row * 16) = vv;
        }
        __syncthreads();

        // S = Q*K^T
        float S[8][4];
        #pragma unroll
        for (int j = 0; j < 8; j++)
            #pragma unroll
            for (int i = 0; i < 4; i++) S[j][i] = 0.0f;

        #pragma unroll
        for (int j = 0; j < 8; j++) {
            unsigned b1[4], b2[4];
            ldsm4(b1, ka + j * 144);
            ldsm4(b2, ka + j * 144 + 4608);   // blocks kk=2,3
            mma_tf32(S[j], aq[0], b1[0], b1[1]);
            mma_tf32(S[j], aq[1], b1[2], b1[3]);
            mma_tf32(S[j], aq[2], b2[0], b2[1]);
            mma_tf32(S[j], aq[3], b2[2], b2[3]);
        }

        // Online softmax (log2 domain).
        float tm0 = -1e30f, tm1 = -1e30f;
        #pragma unroll
        for (int j = 0; j < 8; j++) {
            tm0 = fmaxf(tm0, fmaxf(S[j][0], S[j][1]));
            tm1 = fmaxf(tm1, fmaxf(S[j][2], S[j][3]));
        }
        tm0 = fmaxf(tm0, __shfl_xor_sync(0xffffffffu, tm0, 1));
        tm0 = fmaxf(tm0, __shfl_xor_sync(0xffffffffu, tm0, 2));
        tm1 = fmaxf(tm1, __shfl_xor_sync(0xffffffffu, tm1, 1));
        tm1 = fmaxf(tm1, __shfl_xor_sync(0xffffffffu, tm1, 2));

        float mn0 = fmaxf(m0, tm0), mn1 = fmaxf(m1, tm1);
        float a0 = ex2(m0 - mn0), a1 = ex2(m1 - mn1);
        m0 = mn0; m1 = mn1;

        float rs0 = 0.0f, rs1 = 0.0f;
        #pragma unroll
        for (int j = 0; j < 8; j++) {
            S[j][0] = ex2(S[j][0] - mn0);
            S[j][1] = ex2(S[j][1] - mn0);
            S[j][2] = ex2(S[j][2] - mn1);
            S[j][3] = ex2(S[j][3] - mn1);
            rs0 += S[j][0] + S[j][1];
            rs1 += S[j][2] + S[j][3];
        }
        rs0 += __shfl_xor_sync(0xffffffffu, rs0, 1);
        rs0 += __shfl_xor_sync(0xffffffffu, rs0, 2);
        rs1 += __shfl_xor_sync(0xffffffffu, rs1, 1);
        rs1 += __shfl_xor_sync(0xffffffffu, rs1, 2);
        l0 = l0 * a0 + rs0;
        l1 = l1 * a1 + rs1;

        #pragma unroll
        for (int jn = 0; jn < 4; jn++) {
            O[jn][0] *= a0; O[jn][1] *= a0;
            O[jn][2] *= a1; O[jn][3] *= a1;
        }

        // P -> fp16 A frags (C layout == A layout).
        unsigned ap[4][4];
        #pragma unroll
        for (int jp = 0; jp < 4; jp++) {
            ap[jp][0] = pack_h2(S[2 * jp    ][0], S[2 * jp    ][1]);
            ap[jp][1] = pack_h2(S[2 * jp    ][2], S[2 * jp    ][3]);
            ap[jp][2] = pack_h2(S[2 * jp + 1][0], S[2 * jp + 1][1]);
            ap[jp][3] = pack_h2(S[2 * jp + 1][2], S[2 * jp + 1][3]);
        }

        // O += P * V
        #pragma unroll
        for (int jn = 0; jn < 4; jn++) {
            unsigned b1[4], b2[4];
            ldsm4(b1, va + jn * 144);
            ldsm4(b2, va + jn * 144 + 2304);  // blocks jp=2,3
            mma_f16(O[jn], ap[0], b1[0], b1[1]);
            mma_f16(O[jn], ap[1], b1[2], b1[3]);
            mma_f16(O[jn], ap[2], b2[0], b2[1]);
            mma_f16(O[jn], ap[3], b2[2], b2[3]);
        }
    }

    // Normalize + coalesced writeback via smem.
    float inv0 = 1.0f / l0, inv1 = 1.0f / l1;
    __syncthreads();
    #pragma unroll
    for (int jn = 0; jn < 4; jn++) {
        Qs[q0 + g    ][8 * jn + 2 * c    ] = O[jn][0] * inv0;
        Qs[q0 + g    ][8 * jn + 2 * c + 1] = O[jn][1] * inv0;
        Qs[q0 + g + 8][8 * jn + 2 * c    ] = O[jn][2] * inv1;
        Qs[q0 + g + 8][8 * jn + 2 * c + 1] = O[jn][3] * inv1;
    }
    __syncthreads();

    float* ob = out + base;
    for (int i = tid; i < QT * DK; i += 128) {
        int d = i >> 6;
        int q = i & 63;
        ob[(size_t)d * T_LEN + t0 + q] = Qs[q][d];
    }
}

// ---------------------------------------------------------------------------
extern "C" void kernel_launch(void* const* d_in, const int* in_sizes, int n_in,
                              void* d_out, int out_size)
{
    const float* x  = (const float*)d_in[0];
    const float* Wq = (const float*)d_in[1];
    const float* Wk = (const float*)d_in[2];
    const float* Wv = (const float*)d_in[3];
    float* out = (float*)d_out;

    dim3 pgrid(T_LEN / 64, 12, N_B);
    proj_kernel<<<pgrid, 256>>>(x, Wq, Wk, Wv);

    dim3 agrid(T_LEN / QT, HEADS, N_B);
    attn_kernel<<<agrid, 128>>>(out);
}

// round 8
// speedup vs baseline: 1.3497x; 1.3497x over previous
#include <cuda_runtime.h>
#include <cuda_fp16.h>

#define N_B    4
#define C_IN   256
#define T_LEN  2048
#define HEADS  8
#define DK     32

// Scratch: q (pre-scaled, tf32-rounded bits), k (tf32-rounded bits), v (fp16).
// Layout [N][256][T] (== [N][H][d][T]).
__device__ float  g_q[N_B * C_IN * T_LEN];
__device__ float  g_k[N_B * C_IN * T_LEN];
__device__ __half g_v[N_B * C_IN * T_LEN];

__device__ __forceinline__ unsigned f2tf32(float f) {
    unsigned u;
    asm("cvt.rna.tf32.f32 %0, %1;" : "=r"(u) : "f"(f));
    return u;
}
__device__ __forceinline__ float ex2(float x) {
    float y;
    asm("ex2.approx.f32 %0, %1;" : "=f"(y) : "f"(x));
    return y;
}
__device__ __forceinline__ void mma_tf32(float d[4], const unsigned a[4],
                                         unsigned b0, unsigned b1) {
    asm volatile(
        "mma.sync.aligned.m16n8k8.row.col.f32.tf32.tf32.f32 "
        "{%0,%1,%2,%3}, {%4,%5,%6,%7}, {%8,%9}, {%0,%1,%2,%3};"
        : "+f"(d[0]), "+f"(d[1]), "+f"(d[2]), "+f"(d[3])
        : "r"(a[0]), "r"(a[1]), "r"(a[2]), "r"(a[3]), "r"(b0), "r"(b1));
}
__device__ __forceinline__ void mma_f16(float d[4], const unsigned a[4],
                                        unsigned b0, unsigned b1) {
    asm volatile(
        "mma.sync.aligned.m16n8k16.row.col.f32.f16.f16.f32 "
        "{%0,%1,%2,%3}, {%4,%5,%6,%7}, {%8,%9}, {%0,%1,%2,%3};"
        : "+f"(d[0]), "+f"(d[1]), "+f"(d[2]), "+f"(d[3])
        : "r"(a[0]), "r"(a[1]), "r"(a[2]), "r"(a[3]), "r"(b0), "r"(b1));
}
__device__ __forceinline__ unsigned pack_h2(float x, float y) {
    __half2 h = __floats2half2_rn(x, y);
    return *(unsigned*)&h;
}
__device__ __forceinline__ unsigned su32(const void* p) {
    return (unsigned)__cvta_generic_to_shared(p);
}
__device__ __forceinline__ void cp16(unsigned dst, const void* src) {
    asm volatile("cp.async.cg.shared.global [%0], [%1], 16;"
                 :: "r"(dst), "l"(src));
}
__device__ __forceinline__ void cp_commit() {
    asm volatile("cp.async.commit_group;");
}
template <int N>
__device__ __forceinline__ void cp_wait() {
    asm volatile("cp.async.wait_group %0;" :: "n"(N));
}

// ---------------------------------------------------------------------------
// Projection + format conversion.
//   wsel 0 (q): acc * (1/sqrt(dk) * log2e), tf32-rounded bits.
//   wsel 1 (k): tf32-rounded bits.
//   wsel 2 (v): fp16.
// ---------------------------------------------------------------------------
__global__ __launch_bounds__(256) void proj_kernel(
    const float* __restrict__ x,
    const float* __restrict__ Wq,
    const float* __restrict__ Wk,
    const float* __restrict__ Wv)
{
    __shared__ float Ws[32][65];
    __shared__ float Xs[32][64];

    const int tid = threadIdx.x;
    const int tx  = tid & 15;
    const int ty  = tid >> 4;
    const int t0  = blockIdx.x * 64;
    const int by  = blockIdx.y;
    const int n   = blockIdx.z;
    const int wsel = by >> 2;
    const int o0   = (by & 3) * 64;

    const float* W  = (wsel == 0) ? Wq : (wsel == 1) ? Wk : Wv;
    const float* xb = x + (size_t)n * C_IN * T_LEN;

    float acc[4][4];
    #pragma unroll
    for (int i = 0; i < 4; i++)
        #pragma unroll
        for (int j = 0; j < 4; j++) acc[i][j] = 0.0f;

    for (int c0 = 0; c0 < C_IN; c0 += 32) {
        #pragma unroll
        for (int l = 0; l < 8; l++) {
            int e = l * 256 + tid;
            int o = e >> 5;
            int c = e & 31;
            Ws[c][o] = W[(o0 + o) * C_IN + c0 + c];
        }
        #pragma unroll
        for (int l = 0; l < 8; l++) {
            int e = l * 256 + tid;
            int c = e >> 6;
            int t = e & 63;
            Xs[c][t] = xb[(size_t)(c0 + c) * T_LEN + t0 + t];
        }
        __syncthreads();

        #pragma unroll
        for (int c = 0; c < 32; c++) {
            float wf[4];
            #pragma unroll
            for (int i = 0; i < 4; i++) wf[i] = Ws[c][ty * 4 + i];
            float4 xv = *(const float4*)&Xs[c][tx * 4];
            float xf[4] = {xv.x, xv.y, xv.z, xv.w};
            #pragma unroll
            for (int i = 0; i < 4; i++)
                #pragma unroll
                for (int j = 0; j < 4; j++)
                    acc[i][j] = fmaf(wf[i], xf[j], acc[i][j]);
        }
        __syncthreads();
    }

    const float QS = 0.17677669529663689f * 1.4426950408889634f;

    if (wsel == 0) {
        float* ob = g_q + (size_t)n * C_IN * T_LEN;
        #pragma unroll
        for (int i = 0; i < 4; i++) {
            float4 v = make_float4(
                __uint_as_float(f2tf32(acc[i][0] * QS)),
                __uint_as_float(f2tf32(acc[i][1] * QS)),
                __uint_as_float(f2tf32(acc[i][2] * QS)),
                __uint_as_float(f2tf32(acc[i][3] * QS)));
            *(float4*)&ob[(size_t)(o0 + ty * 4 + i) * T_LEN + t0 + tx * 4] = v;
        }
    } else if (wsel == 1) {
        float* ob = g_k + (size_t)n * C_IN * T_LEN;
        #pragma unroll
        for (int i = 0; i < 4; i++) {
            float4 v = make_float4(
                __uint_as_float(f2tf32(acc[i][0])),
                __uint_as_float(f2tf32(acc[i][1])),
                __uint_as_float(f2tf32(acc[i][2])),
                __uint_as_float(f2tf32(acc[i][3])));
            *(float4*)&ob[(size_t)(o0 + ty * 4 + i) * T_LEN + t0 + tx * 4] = v;
        }
    } else {
        __half* ob = g_v + (size_t)n * C_IN * T_LEN;
        #pragma unroll
        for (int i = 0; i < 4; i++) {
            uint2 v;
            v.x = pack_h2(acc[i][0], acc[i][1]);
            v.y = pack_h2(acc[i][2], acc[i][3]);
            *(uint2*)&ob[(size_t)(o0 + ty * 4 + i) * T_LEN + t0 + tx * 4] = v;
        }
    }
}

// ---------------------------------------------------------------------------
// Tensor-core flash attention (round-2 compute) + cp.async double buffering.
//   CTA: 64 queries, 4 warps (16 q-rows each). K-tile = 64 keys.
//   Ks: tf32 bits [d=32][key=64] stride 72 (conflict-free B-frag LDS).
//   Vs: fp16      [dv=32][key=64] stride 72.
//   Both double-buffered; tiles prefetched with cp.async.cg 16B.
//   K tile: 32 rows x 16 chunks (16B) = 512 chunks; 4 per thread.
//   V tile: 32 rows x  8 chunks (16B) = 256 chunks; 2 per thread.
// grid = (T/64, H, N), block = 128.
// ---------------------------------------------------------------------------
#define QT 64
#define KT 64
#define NTILES (T_LEN / KT)

__global__ __launch_bounds__(128) void attn_kernel(float* __restrict__ out)
{
    __shared__ __align__(16) unsigned Ks[2][32 * 72];   // 18432 B
    __shared__ __align__(16) __half   Vs[2][32 * 72];   //  9216 B
    __shared__ float Qs[64][33];                        //  8448 B

    const int tid  = threadIdx.x;
    const int warp = tid >> 5;
    const int lane = tid & 31;
    const int g    = lane >> 2;
    const int c    = lane & 3;

    const int t0 = blockIdx.x * QT;
    const int h  = blockIdx.y;
    const int n  = blockIdx.z;

    const size_t base = ((size_t)n * HEADS + h) * DK * T_LEN;
    const float*  qb = g_q + base;
    const float*  kb = g_k + base;
    const __half* vb = g_v + base;

    const unsigned ksb = su32(Ks);
    const unsigned vsb = su32(Vs);

    // Stage Q (pre-scaled tf32 bits) transposed to [q][d].
    for (int i = tid; i < QT * DK / 4; i += 128) {
        int d  = i >> 4;
        int q4 = (i & 15) * 4;
        float4 v = *(const float4*)&qb[(size_t)d * T_LEN + t0 + q4];
        Qs[q4 + 0][d] = v.x; Qs[q4 + 1][d] = v.y;
        Qs[q4 + 2][d] = v.z; Qs[q4 + 3][d] = v.w;
    }

    // Prefetch tile 0 into buffer 0.
    {
        #pragma unroll
        for (int l = 0; l < 4; l++) {
            int idx = l * 128 + tid;          // 0..511
            int d   = idx >> 4;               // 0..31
            int k4  = (idx & 15) * 4;         // 0..60 floats
            cp16(ksb + (unsigned)(d * 72 + k4) * 4, &kb[(size_t)d * T_LEN + k4]);
        }
        #pragma unroll
        for (int l = 0; l < 2; l++) {
            int idx = l * 128 + tid;          // 0..255
            int dv  = idx >> 3;               // 0..31
            int k8  = (idx & 7) * 8;          // 0..56 halves
            cp16(vsb + (unsigned)(dv * 72 + k8) * 2, &vb[(size_t)dv * T_LEN + k8]);
        }
        cp_commit();
    }
    __syncthreads();

    const int q0 = warp * 16;
    unsigned aq[4][4];
    #pragma unroll
    for (int kk = 0; kk < 4; kk++) {
        aq[kk][0] = __float_as_uint(Qs[q0 + g    ][kk * 8 + c    ]);
        aq[kk][1] = __float_as_uint(Qs[q0 + g + 8][kk * 8 + c    ]);
        aq[kk][2] = __float_as_uint(Qs[q0 + g    ][kk * 8 + c + 4]);
        aq[kk][3] = __float_as_uint(Qs[q0 + g + 8][kk * 8 + c + 4]);
    }

    float O[4][4];
    #pragma unroll
    for (int jn = 0; jn < 4; jn++)
        #pragma unroll
        for (int i = 0; i < 4; i++) O[jn][i] = 0.0f;
    float m0 = -1e30f, m1 = -1e30f, l0 = 0.0f, l1 = 0.0f;

    for (int it = 0; it < NTILES; it++) {
        const int buf = it & 1;

        // Prefetch tile it+1 into the other buffer (drained at last iter's sync).
        if (it + 1 < NTILES) {
            const int s1 = (it + 1) * KT;
            const unsigned kdst = ksb + (unsigned)(1 - buf) * (32 * 72 * 4);
            const unsigned vdst = vsb + (unsigned)(1 - buf) * (32 * 72 * 2);
            #pragma unroll
            for (int l = 0; l < 4; l++) {
                int idx = l * 128 + tid;
                int d   = idx >> 4;
                int k4  = (idx & 15) * 4;
                cp16(kdst + (unsigned)(d * 72 + k4) * 4,
                     &kb[(size_t)d * T_LEN + s1 + k4]);
            }
            #pragma unroll
            for (int l = 0; l < 2; l++) {
                int idx = l * 128 + tid;
                int dv  = idx >> 3;
                int k8  = (idx & 7) * 8;
                cp16(vdst + (unsigned)(dv * 72 + k8) * 2,
                     &vb[(size_t)dv * T_LEN + s1 + k8]);
            }
            cp_commit();
            cp_wait<1>();   // tile `it` complete; it+1 still in flight
        } else {
            cp_wait<0>();
        }
        __syncthreads();

        const unsigned* K   = Ks[buf];
        const unsigned* Vsu = (const unsigned*)Vs[buf];

        // S = Q*K^T : 8 n-blocks x 4 k-steps of m16n8k8 tf32.
        float S[8][4];
        #pragma unroll
        for (int j = 0; j < 8; j++)
            #pragma unroll
            for (int i = 0; i < 4; i++) S[j][i] = 0.0f;

        #pragma unroll
        for (int j = 0; j < 8; j++) {
            #pragma unroll
            for (int kk = 0; kk < 4; kk++) {
                unsigned b0 = K[(kk * 8 + c    ) * 72 + j * 8 + g];
                unsigned b1 = K[(kk * 8 + c + 4) * 72 + j * 8 + g];
                mma_tf32(S[j], aq[kk], b0, b1);
            }
        }

        // Online softmax (log2 domain).
        float tm0 = -1e30f, tm1 = -1e30f;
        #pragma unroll
        for (int j = 0; j < 8; j++) {
            tm0 = fmaxf(tm0, fmaxf(S[j][0], S[j][1]));
            tm1 = fmaxf(tm1, fmaxf(S[j][2], S[j][3]));
        }
        tm0 = fmaxf(tm0, __shfl_xor_sync(0xffffffffu, tm0, 1));
        tm0 = fmaxf(tm0, __shfl_xor_sync(0xffffffffu, tm0, 2));
        tm1 = fmaxf(tm1, __shfl_xor_sync(0xffffffffu, tm1, 1));
        tm1 = fmaxf(tm1, __shfl_xor_sync(0xffffffffu, tm1, 2));

        float mn0 = fmaxf(m0, tm0), mn1 = fmaxf(m1, tm1);
        float a0 = ex2(m0 - mn0), a1 = ex2(m1 - mn1);
        m0 = mn0; m1 = mn1;

        float rs0 = 0.0f, rs1 = 0.0f;
        #pragma unroll
        for (int j = 0; j < 8; j++) {
            S[j][0] = ex2(S[j][0] - mn0);
            S[j][1] = ex2(S[j][1] - mn0);
            S[j][2] = ex2(S[j][2] - mn1);
            S[j][3] = ex2(S[j][3] - mn1);
            rs0 += S[j][0] + S[j][1];
            rs1 += S[j][2] + S[j][3];
        }
        rs0 += __shfl_xor_sync(0xffffffffu, rs0, 1);
        rs0 += __shfl_xor_sync(0xffffffffu, rs0, 2);
        rs1 += __shfl_xor_sync(0xffffffffu, rs1, 1);
        rs1 += __shfl_xor_sync(0xffffffffu, rs1, 2);
        l0 = l0 * a0 + rs0;
        l1 = l1 * a1 + rs1;

        #pragma unroll
        for (int jn = 0; jn < 4; jn++) {
            O[jn][0] *= a0; O[jn][1] *= a0;
            O[jn][2] *= a1; O[jn][3] *= a1;
        }

        // P -> fp16 A frags (C layout == A layout for m16n8k16).
        unsigned ap[4][4];
        #pragma unroll
        for (int jp = 0; jp < 4; jp++) {
            ap[jp][0] = pack_h2(S[2 * jp    ][0], S[2 * jp    ][1]);
            ap[jp][1] = pack_h2(S[2 * jp    ][2], S[2 * jp    ][3]);
            ap[jp][2] = pack_h2(S[2 * jp + 1][0], S[2 * jp + 1][1]);
            ap[jp][3] = pack_h2(S[2 * jp + 1][2], S[2 * jp + 1][3]);
        }

        // O += P * V : 4 dv-blocks x 4 k-steps of m16n8k16 fp16.
        #pragma unroll
        for (int jn = 0; jn < 4; jn++) {
            #pragma unroll
            for (int jp = 0; jp < 4; jp++) {
                unsigned b0 = Vsu[(8 * jn + g) * 36 + 8 * jp + c    ];
                unsigned b1 = Vsu[(8 * jn + g) * 36 + 8 * jp + c + 4];
                mma_f16(O[jn], ap[jp], b0, b1);
            }
        }

        __syncthreads();   // buffer `buf` free for prefetch next iteration
    }

    // Normalize + coalesced writeback via smem.
    float inv0 = 1.0f / l0, inv1 = 1.0f / l1;
    #pragma unroll
    for (int jn = 0; jn < 4; jn++) {
        Qs[q0 + g    ][8 * jn + 2 * c    ] = O[jn][0] * inv0;
        Qs[q0 + g    ][8 * jn + 2 * c + 1] = O[jn][1] * inv0;
        Qs[q0 + g + 8][8 * jn + 2 * c    ] = O[jn][2] * inv1;
        Qs[q0 + g + 8][8 * jn + 2 * c + 1] = O[jn][3] * inv1;
    }
    __syncthreads();

    float* ob = out + base;
    for (int i = tid; i < QT * DK; i += 128) {
        int d = i >> 6;
        int q = i & 63;
        ob[(size_t)d * T_LEN + t0 + q] = Qs[q][d];
    }
}

// ---------------------------------------------------------------------------
extern "C" void kernel_launch(void* const* d_in, const int* in_sizes, int n_in,
                              void* d_out, int out_size)
{
    const float* x  = (const float*)d_in[0];
    const float* Wq = (const float*)d_in[1];
    const float* Wk = (const float*)d_in[2];
    const float* Wv = (const float*)d_in[3];
    float* out = (float*)d_out;

    dim3 pgrid(T_LEN / 64, 12, N_B);
    proj_kernel<<<pgrid, 256>>>(x, Wq, Wk, Wv);

    dim3 agrid(T_LEN / QT, HEADS, N_B);
    attn_kernel<<<agrid, 128>>>(out);
}

// round 10
// speedup vs baseline: 1.9357x; 1.4342x over previous
#include <cuda_runtime.h>
#include <cuda_fp16.h>

#define N_B    4
#define C_IN   256
#define T_LEN  2048
#define HEADS  8
#define DK     32

// Scratch. q/k: tf32-bit fp32 (q pre-scaled). v: fp16. Layout [N][256][T].
__device__ float    g_q[N_B * C_IN * T_LEN];
__device__ float    g_k[N_B * C_IN * T_LEN];
__device__ __half   g_v[N_B * C_IN * T_LEN];
// Pre-converted tf32 operands for the projection GEMM.
__device__ unsigned g_xt[N_B * C_IN * T_LEN];      // x as tf32 bits
__device__ unsigned g_wt[3 * C_IN * C_IN];         // Wq*QS, Wk, Wv as tf32 bits

__device__ __forceinline__ unsigned f2tf32(float f) {
    unsigned u;
    asm("cvt.rna.tf32.f32 %0, %1;" : "=r"(u) : "f"(f));
    return u;
}
__device__ __forceinline__ float ex2(float x) {
    float y;
    asm("ex2.approx.f32 %0, %1;" : "=f"(y) : "f"(x));
    return y;
}
__device__ __forceinline__ void mma_tf32(float d[4], const unsigned a[4],
                                         unsigned b0, unsigned b1) {
    asm volatile(
        "mma.sync.aligned.m16n8k8.row.col.f32.tf32.tf32.f32 "
        "{%0,%1,%2,%3}, {%4,%5,%6,%7}, {%8,%9}, {%0,%1,%2,%3};"
        : "+f"(d[0]), "+f"(d[1]), "+f"(d[2]), "+f"(d[3])
        : "r"(a[0]), "r"(a[1]), "r"(a[2]), "r"(a[3]), "r"(b0), "r"(b1));
}
__device__ __forceinline__ void mma_f16(float d[4], const unsigned a[4],
                                        unsigned b0, unsigned b1) {
    asm volatile(
        "mma.sync.aligned.m16n8k16.row.col.f32.f16.f16.f32 "
        "{%0,%1,%2,%3}, {%4,%5,%6,%7}, {%8,%9}, {%0,%1,%2,%3};"
        : "+f"(d[0]), "+f"(d[1]), "+f"(d[2]), "+f"(d[3])
        : "r"(a[0]), "r"(a[1]), "r"(a[2]), "r"(a[3]), "r"(b0), "r"(b1));
}
__device__ __forceinline__ unsigned pack_h2(float x, float y) {
    __half2 h = __floats2half2_rn(x, y);
    return *(unsigned*)&h;
}
__device__ __forceinline__ unsigned su32(const void* p) {
    return (unsigned)__cvta_generic_to_shared(p);
}
__device__ __forceinline__ void cp16(unsigned dst, const void* src) {
    asm volatile("cp.async.cg.shared.global [%0], [%1], 16;"
                 :: "r"(dst), "l"(src));
}
__device__ __forceinline__ void cp_commit() {
    asm volatile("cp.async.commit_group;");
}
template <int N>
__device__ __forceinline__ void cp_wait() {
    asm volatile("cp.async.wait_group %0;" :: "n"(N));
}

// ---------------------------------------------------------------------------
// Prep: convert x -> tf32 bits (g_xt); W -> tf32 bits (g_wt), QS folded into Wq.
// ---------------------------------------------------------------------------
__global__ __launch_bounds__(256) void prep_kernel(
    const float* __restrict__ x,
    const float* __restrict__ Wq,
    const float* __restrict__ Wk,
    const float* __restrict__ Wv)
{
    const int stride = gridDim.x * blockDim.x;
    const int i0 = blockIdx.x * blockDim.x + threadIdx.x;
    const float QS = 0.17677669529663689f * 1.4426950408889634f;

    for (int i = i0; i < (N_B * C_IN * T_LEN) / 4; i += stride) {
        float4 v = ((const float4*)x)[i];
        uint4 o;
        o.x = f2tf32(v.x); o.y = f2tf32(v.y);
        o.z = f2tf32(v.z); o.w = f2tf32(v.w);
        ((uint4*)g_xt)[i] = o;
    }
    for (int i = i0; i < (C_IN * C_IN) / 4; i += stride) {
        float4 a = ((const float4*)Wq)[i];
        uint4 o;
        o.x = f2tf32(a.x * QS); o.y = f2tf32(a.y * QS);
        o.z = f2tf32(a.z * QS); o.w = f2tf32(a.w * QS);
        ((uint4*)g_wt)[i] = o;
        float4 b = ((const float4*)Wk)[i];
        o.x = f2tf32(b.x); o.y = f2tf32(b.y); o.z = f2tf32(b.z); o.w = f2tf32(b.w);
        ((uint4*)(g_wt + C_IN * C_IN))[i] = o;
        float4 c = ((const float4*)Wv)[i];
        o.x = f2tf32(c.x); o.y = f2tf32(c.y); o.z = f2tf32(c.z); o.w = f2tf32(c.w);
        ((uint4*)(g_wt + 2 * C_IN * C_IN))[i] = o;
    }
}

// ---------------------------------------------------------------------------
// Tensor-core projection: y[o][t] = sum_c W[o][c] * x[c][t].
//   Same A*B^T shape as QK^T: A = W (rows o, K = c), B = x^T (rows t, K = c).
//   CTA: 64 o (4 warps x 16) x 64 t. K-loop: 8 chunks of 32 c,
//   cp.async double-buffered. Epilogue converts per wsel (q/k tf32, v fp16).
// grid = (T/64, 12, N): blockIdx.y -> wsel = y>>2, o0 = (y&3)*64.
// ---------------------------------------------------------------------------
__global__ __launch_bounds__(128) void proj_tc_kernel()
{
    __shared__ __align__(16) unsigned Xs[2][32 * 72];   // [c][t], 18432 B
    __shared__ __align__(16) unsigned Ws[2][64 * 36];   // [o][c], 18432 B

    const int tid  = threadIdx.x;
    const int warp = tid >> 5;
    const int lane = tid & 31;
    const int g    = lane >> 2;
    const int c    = lane & 3;

    const int t0   = blockIdx.x * 64;
    const int wsel = blockIdx.y >> 2;
    const int o0   = (blockIdx.y & 3) * 64;
    const int n    = blockIdx.z;

    const unsigned* xt = g_xt + (size_t)n * C_IN * T_LEN;
    const unsigned* wt = g_wt + wsel * C_IN * C_IN + o0 * C_IN;

    const unsigned xsb = su32(Xs);
    const unsigned wsb = su32(Ws);

    // Stage one K-chunk (32 c): X tile 32x64 (512 x 16B), W tile 64x32 (512 x 16B).
    auto stage = [&](int buf, int c0) {
        const unsigned xdst = xsb + (unsigned)buf * (32 * 72 * 4);
        const unsigned wdst = wsb + (unsigned)buf * (64 * 36 * 4);
        #pragma unroll
        for (int l = 0; l < 4; l++) {
            int idx = l * 128 + tid;           // 0..511
            int cc  = idx >> 4;                // 0..31
            int t4  = (idx & 15) * 4;
            cp16(xdst + (unsigned)(cc * 72 + t4) * 4,
                 &xt[(size_t)(c0 + cc) * T_LEN + t0 + t4]);
        }
        #pragma unroll
        for (int l = 0; l < 4; l++) {
            int idx = l * 128 + tid;           // 0..511
            int o   = idx >> 3;                // 0..63
            int c4  = (idx & 7) * 4;           // 0..28
            cp16(wdst + (unsigned)(o * 36 + c4) * 4,
                 &wt[o * C_IN + c0 + c4]);
        }
    };

    stage(0, 0);
    cp_commit();

    const int ow = warp * 16;
    float C[8][4];
    #pragma unroll
    for (int j = 0; j < 8; j++)
        #pragma unroll
        for (int i = 0; i < 4; i++) C[j][i] = 0.0f;

    #pragma unroll 1
    for (int ch = 0; ch < C_IN / 32; ch++) {
        const int buf = ch & 1;
        if (ch + 1 < C_IN / 32) {
            stage(1 - buf, (ch + 1) * 32);
            cp_commit();
            cp_wait<1>();
        } else {
            cp_wait<0>();
        }
        __syncthreads();

        const unsigned* W = Ws[buf];
        const unsigned* X = Xs[buf];

        unsigned a[4][4];
        #pragma unroll
        for (int kk = 0; kk < 4; kk++) {
            a[kk][0] = W[(ow + g    ) * 36 + kk * 8 + c    ];
            a[kk][1] = W[(ow + g + 8) * 36 + kk * 8 + c    ];
            a[kk][2] = W[(ow + g    ) * 36 + kk * 8 + c + 4];
            a[kk][3] = W[(ow + g + 8) * 36 + kk * 8 + c + 4];
        }

        #pragma unroll
        for (int j = 0; j < 8; j++) {
            #pragma unroll
            for (int kk = 0; kk < 4; kk++) {
                unsigned b0 = X[(kk * 8 + c    ) * 72 + j * 8 + g];
                unsigned b1 = X[(kk * 8 + c + 4) * 72 + j * 8 + g];
                mma_tf32(C[j], a[kk], b0, b1);
            }
        }
        __syncthreads();
    }

    // Epilogue. Rows r0 = o0+ow+g, r1 = r0+8; cols t0 + j*8 + 2c, +1.
    const int r0 = o0 + ow + g;
    const size_t obase = (size_t)n * C_IN * T_LEN;

    if (wsel < 2) {
        float* ob = (wsel == 0 ? g_q : g_k) + obase;
        #pragma unroll
        for (int j = 0; j < 8; j++) {
            int tcol = t0 + j * 8 + 2 * c;
            uint2 s0, s1;
            s0.x = f2tf32(C[j][0]); s0.y = f2tf32(C[j][1]);
            s1.x = f2tf32(C[j][2]); s1.y = f2tf32(C[j][3]);
            *(uint2*)&ob[(size_t)r0 * T_LEN + tcol]       = s0;
            *(uint2*)&ob[(size_t)(r0 + 8) * T_LEN + tcol] = s1;
        }
    } else {
        __half* ob = g_v + obase;
        #pragma unroll
        for (int j = 0; j < 8; j++) {
            int tcol = t0 + j * 8 + 2 * c;
            *(unsigned*)&ob[(size_t)r0 * T_LEN + tcol]       = pack_h2(C[j][0], C[j][1]);
            *(unsigned*)&ob[(size_t)(r0 + 8) * T_LEN + tcol] = pack_h2(C[j][2], C[j][3]);
        }
    }
}

// ---------------------------------------------------------------------------
// Tensor-core flash attention (unchanged from round 8: 103 us).
// ---------------------------------------------------------------------------
#define QT 64
#define KT 64
#define NTILES (T_LEN / KT)

__global__ __launch_bounds__(128) void attn_kernel(float* __restrict__ out)
{
    __shared__ __align__(16) unsigned Ks[2][32 * 72];   // 18432 B
    __shared__ __align__(16) __half   Vs[2][32 * 72];   //  9216 B
    __shared__ float Qs[64][33];                        //  8448 B

    const int tid  = threadIdx.x;
    const int warp = tid >> 5;
    const int lane = tid & 31;
    const int g    = lane >> 2;
    const int c    = lane & 3;

    const int t0 = blockIdx.x * QT;
    const int h  = blockIdx.y;
    const int n  = blockIdx.z;

    const size_t base = ((size_t)n * HEADS + h) * DK * T_LEN;
    const float*  qb = g_q + base;
    const float*  kb = g_k + base;
    const __half* vb = g_v + base;

    const unsigned ksb = su32(Ks);
    const unsigned vsb = su32(Vs);

    // Stage Q (pre-scaled tf32 bits) transposed to [q][d].
    for (int i = tid; i < QT * DK / 4; i += 128) {
        int d  = i >> 4;
        int q4 = (i & 15) * 4;
        float4 v = *(const float4*)&qb[(size_t)d * T_LEN + t0 + q4];
        Qs[q4 + 0][d] = v.x; Qs[q4 + 1][d] = v.y;
        Qs[q4 + 2][d] = v.z; Qs[q4 + 3][d] = v.w;
    }

    // Prefetch tile 0 into buffer 0.
    {
        #pragma unroll
        for (int l = 0; l < 4; l++) {
            int idx = l * 128 + tid;          // 0..511
            int d   = idx >> 4;               // 0..31
            int k4  = (idx & 15) * 4;
            cp16(ksb + (unsigned)(d * 72 + k4) * 4, &kb[(size_t)d * T_LEN + k4]);
        }
        #pragma unroll
        for (int l = 0; l < 2; l++) {
            int idx = l * 128 + tid;          // 0..255
            int dv  = idx >> 3;               // 0..31
            int k8  = (idx & 7) * 8;
            cp16(vsb + (unsigned)(dv * 72 + k8) * 2, &vb[(size_t)dv * T_LEN + k8]);
        }
        cp_commit();
    }
    __syncthreads();

    const int q0 = warp * 16;
    unsigned aq[4][4];
    #pragma unroll
    for (int kk = 0; kk < 4; kk++) {
        aq[kk][0] = __float_as_uint(Qs[q0 + g    ][kk * 8 + c    ]);
        aq[kk][1] = __float_as_uint(Qs[q0 + g + 8][kk * 8 + c    ]);
        aq[kk][2] = __float_as_uint(Qs[q0 + g    ][kk * 8 + c + 4]);
        aq[kk][3] = __float_as_uint(Qs[q0 + g + 8][kk * 8 + c + 4]);
    }

    float O[4][4];
    #pragma unroll
    for (int jn = 0; jn < 4; jn++)
        #pragma unroll
        for (int i = 0; i < 4; i++) O[jn][i] = 0.0f;
    float m0 = -1e30f, m1 = -1e30f, l0 = 0.0f, l1 = 0.0f;

    for (int it = 0; it < NTILES; it++) {
        const int buf = it & 1;

        if (it + 1 < NTILES) {
            const int s1 = (it + 1) * KT;
            const unsigned kdst = ksb + (unsigned)(1 - buf) * (32 * 72 * 4);
            const unsigned vdst = vsb + (unsigned)(1 - buf) * (32 * 72 * 2);
            #pragma unroll
            for (int l = 0; l < 4; l++) {
                int idx = l * 128 + tid;
                int d   = idx >> 4;
                int k4  = (idx & 15) * 4;
                cp16(kdst + (unsigned)(d * 72 + k4) * 4,
                     &kb[(size_t)d * T_LEN + s1 + k4]);
            }
            #pragma unroll
            for (int l = 0; l < 2; l++) {
                int idx = l * 128 + tid;
                int dv  = idx >> 3;
                int k8  = (idx & 7) * 8;
                cp16(vdst + (unsigned)(dv * 72 + k8) * 2,
                     &vb[(size_t)dv * T_LEN + s1 + k8]);
            }
            cp_commit();
            cp_wait<1>();
        } else {
            cp_wait<0>();
        }
        __syncthreads();

        const unsigned* K   = Ks[buf];
        const unsigned* Vsu = (const unsigned*)Vs[buf];

        float S[8][4];
        #pragma unroll
        for (int j = 0; j < 8; j++)
            #pragma unroll
            for (int i = 0; i < 4; i++) S[j][i] = 0.0f;

        #pragma unroll
        for (int j = 0; j < 8; j++) {
            #pragma unroll
            for (int kk = 0; kk < 4; kk++) {
                unsigned b0 = K[(kk * 8 + c    ) * 72 + j * 8 + g];
                unsigned b1 = K[(kk * 8 + c + 4) * 72 + j * 8 + g];
                mma_tf32(S[j], aq[kk], b0, b1);
            }
        }

        float tm0 = -1e30f, tm1 = -1e30f;
        #pragma unroll
        for (int j = 0; j < 8; j++) {
            tm0 = fmaxf(tm0, fmaxf(S[j][0], S[j][1]));
            tm1 = fmaxf(tm1, fmaxf(S[j][2], S[j][3]));
        }
        tm0 = fmaxf(tm0, __shfl_xor_sync(0xffffffffu, tm0, 1));
        tm0 = fmaxf(tm0, __shfl_xor_sync(0xffffffffu, tm0, 2));
        tm1 = fmaxf(tm1, __shfl_xor_sync(0xffffffffu, tm1, 1));
        tm1 = fmaxf(tm1, __shfl_xor_sync(0xffffffffu, tm1, 2));

        float mn0 = fmaxf(m0, tm0), mn1 = fmaxf(m1, tm1);
        float a0 = ex2(m0 - mn0), a1 = ex2(m1 - mn1);
        m0 = mn0; m1 = mn1;

        float rs0 = 0.0f, rs1 = 0.0f;
        #pragma unroll
        for (int j = 0; j < 8; j++) {
            S[j][0] = ex2(S[j][0] - mn0);
            S[j][1] = ex2(S[j][1] - mn0);
            S[j][2] = ex2(S[j][2] - mn1);
            S[j][3] = ex2(S[j][3] - mn1);
            rs0 += S[j][0] + S[j][1];
            rs1 += S[j][2] + S[j][3];
        }
        rs0 += __shfl_xor_sync(0xffffffffu, rs0, 1);
        rs0 += __shfl_xor_sync(0xffffffffu, rs0, 2);
        rs1 += __shfl_xor_sync(0xffffffffu, rs1, 1);
        rs1 += __shfl_xor_sync(0xffffffffu, rs1, 2);
        l0 = l0 * a0 + rs0;
        l1 = l1 * a1 + rs1;

        #pragma unroll
        for (int jn = 0; jn < 4; jn++) {
            O[jn][0] *= a0; O[jn][1] *= a0;
            O[jn][2] *= a1; O[jn][3] *= a1;
        }

        unsigned ap[4][4];
        #pragma unroll
        for (int jp = 0; jp < 4; jp++) {
            ap[jp][0] = pack_h2(S[2 * jp    ][0], S[2 * jp    ][1]);
            ap[jp][1] = pack_h2(S[2 * jp    ][2], S[2 * jp    ][3]);
            ap[jp][2] = pack_h2(S[2 * jp + 1][0], S[2 * jp + 1][1]);
            ap[jp][3] = pack_h2(S[2 * jp + 1][2], S[2 * jp + 1][3]);
        }

        #pragma unroll
        for (int jn = 0; jn < 4; jn++) {
            #pragma unroll
            for (int jp = 0; jp < 4; jp++) {
                unsigned b0 = Vsu[(8 * jn + g) * 36 + 8 * jp + c    ];
                unsigned b1 = Vsu[(8 * jn + g) * 36 + 8 * jp + c + 4];
                mma_f16(O[jn], ap[jp], b0, b1);
            }
        }

        __syncthreads();
    }

    float inv0 = 1.0f / l0, inv1 = 1.0f / l1;
    #pragma unroll
    for (int jn = 0; jn < 4; jn++) {
        Qs[q0 + g    ][8 * jn + 2 * c    ] = O[jn][0] * inv0;
        Qs[q0 + g    ][8 * jn + 2 * c + 1] = O[jn][1] * inv0;
        Qs[q0 + g + 8][8 * jn + 2 * c    ] = O[jn][2] * inv1;
        Qs[q0 + g + 8][8 * jn + 2 * c + 1] = O[jn][3] * inv1;
    }
    __syncthreads();

    float* ob = out + base;
    for (int i = tid; i < QT * DK; i += 128) {
        int d = i >> 6;
        int q = i & 63;
        ob[(size_t)d * T_LEN + t0 + q] = Qs[q][d];
    }
}

// ---------------------------------------------------------------------------
extern "C" void kernel_launch(void* const* d_in, const int* in_sizes, int n_in,
                              void* d_out, int out_size)
{
    const float* x  = (const float*)d_in[0];
    const float* Wq = (const float*)d_in[1];
    const float* Wk = (const float*)d_in[2];
    const float* Wv = (const float*)d_in[3];
    float* out = (float*)d_out;

    prep_kernel<<<512, 256>>>(x, Wq, Wk, Wv);

    dim3 pgrid(T_LEN / 64, 12, N_B);
    proj_tc_kernel<<<pgrid, 128>>>();

    dim3 agrid(T_LEN / QT, HEADS, N_B);
    attn_kernel<<<agrid, 128>>>(out);
}

// round 11
// speedup vs baseline: 2.2842x; 1.1801x over previous
#include <cuda_runtime.h>
#include <cuda_fp16.h>

#define N_B    4
#define C_IN   256
#define T_LEN  2048
#define HEADS  8
#define DK     32

// Scratch.
//  g_qh/g_kh: fp16, TRANSPOSED layout [N][H][T][32] (d contiguous; q pre-scaled).
//  g_v:       fp16, [N][256][T] (== [N][H][dv][T]).
//  g_xt/g_wt: tf32 bits for the projection GEMM.
__device__ __half   g_qh[N_B * HEADS * T_LEN * DK];
__device__ __half   g_kh[N_B * HEADS * T_LEN * DK];
__device__ __half   g_v [N_B * C_IN * T_LEN];
__device__ unsigned g_xt[N_B * C_IN * T_LEN];
__device__ unsigned g_wt[3 * C_IN * C_IN];

__device__ __forceinline__ unsigned f2tf32(float f) {
    unsigned u;
    asm("cvt.rna.tf32.f32 %0, %1;" : "=r"(u) : "f"(f));
    return u;
}
__device__ __forceinline__ float ex2(float x) {
    float y;
    asm("ex2.approx.f32 %0, %1;" : "=f"(y) : "f"(x));
    return y;
}
__device__ __forceinline__ void mma_tf32(float d[4], const unsigned a[4],
                                         unsigned b0, unsigned b1) {
    asm volatile(
        "mma.sync.aligned.m16n8k8.row.col.f32.tf32.tf32.f32 "
        "{%0,%1,%2,%3}, {%4,%5,%6,%7}, {%8,%9}, {%0,%1,%2,%3};"
        : "+f"(d[0]), "+f"(d[1]), "+f"(d[2]), "+f"(d[3])
        : "r"(a[0]), "r"(a[1]), "r"(a[2]), "r"(a[3]), "r"(b0), "r"(b1));
}
__device__ __forceinline__ void mma_f16(float d[4], const unsigned a[4],
                                        unsigned b0, unsigned b1) {
    asm volatile(
        "mma.sync.aligned.m16n8k16.row.col.f32.f16.f16.f32 "
        "{%0,%1,%2,%3}, {%4,%5,%6,%7}, {%8,%9}, {%0,%1,%2,%3};"
        : "+f"(d[0]), "+f"(d[1]), "+f"(d[2]), "+f"(d[3])
        : "r"(a[0]), "r"(a[1]), "r"(a[2]), "r"(a[3]), "r"(b0), "r"(b1));
}
__device__ __forceinline__ unsigned pack_h2(float x, float y) {
    __half2 h = __floats2half2_rn(x, y);
    return *(unsigned*)&h;
}
__device__ __forceinline__ unsigned su32(const void* p) {
    return (unsigned)__cvta_generic_to_shared(p);
}
__device__ __forceinline__ void cp16(unsigned dst, const void* src) {
    asm volatile("cp.async.cg.shared.global [%0], [%1], 16;"
                 :: "r"(dst), "l"(src));
}
__device__ __forceinline__ void cp_commit() {
    asm volatile("cp.async.commit_group;");
}
template <int N>
__device__ __forceinline__ void cp_wait() {
    asm volatile("cp.async.wait_group %0;" :: "n"(N));
}

// ---------------------------------------------------------------------------
// Prep: x -> tf32 bits; W -> tf32 bits (QS folded into Wq). (unchanged)
// ---------------------------------------------------------------------------
__global__ __launch_bounds__(256) void prep_kernel(
    const float* __restrict__ x,
    const float* __restrict__ Wq,
    const float* __restrict__ Wk,
    const float* __restrict__ Wv)
{
    const int stride = gridDim.x * blockDim.x;
    const int i0 = blockIdx.x * blockDim.x + threadIdx.x;
    const float QS = 0.17677669529663689f * 1.4426950408889634f;

    for (int i = i0; i < (N_B * C_IN * T_LEN) / 4; i += stride) {
        float4 v = ((const float4*)x)[i];
        uint4 o;
        o.x = f2tf32(v.x); o.y = f2tf32(v.y);
        o.z = f2tf32(v.z); o.w = f2tf32(v.w);
        ((uint4*)g_xt)[i] = o;
    }
    for (int i = i0; i < (C_IN * C_IN) / 4; i += stride) {
        float4 a = ((const float4*)Wq)[i];
        uint4 o;
        o.x = f2tf32(a.x * QS); o.y = f2tf32(a.y * QS);
        o.z = f2tf32(a.z * QS); o.w = f2tf32(a.w * QS);
        ((uint4*)g_wt)[i] = o;
        float4 b = ((const float4*)Wk)[i];
        o.x = f2tf32(b.x); o.y = f2tf32(b.y); o.z = f2tf32(b.z); o.w = f2tf32(b.w);
        ((uint4*)(g_wt + C_IN * C_IN))[i] = o;
        float4 c = ((const float4*)Wv)[i];
        o.x = f2tf32(c.x); o.y = f2tf32(c.y); o.z = f2tf32(c.z); o.w = f2tf32(c.w);
        ((uint4*)(g_wt + 2 * C_IN * C_IN))[i] = o;
    }
}

// ---------------------------------------------------------------------------
// Tensor-core projection (tf32 compute unchanged).
// Epilogue: wsel 0/1 (q/k) -> smem transpose -> fp16 [n][h][t][d].
//           wsel 2   (v)   -> fp16 [dv][t].
// ---------------------------------------------------------------------------
__global__ __launch_bounds__(128) void proj_tc_kernel()
{
    __shared__ __align__(16) unsigned Xs[2][32 * 72];   // [c][t]
    __shared__ __align__(16) unsigned Ws[2][64 * 36];   // [o][c]

    const int tid  = threadIdx.x;
    const int warp = tid >> 5;
    const int lane = tid & 31;
    const int g    = lane >> 2;
    const int c    = lane & 3;

    const int t0   = blockIdx.x * 64;
    const int wsel = blockIdx.y >> 2;
    const int o0   = (blockIdx.y & 3) * 64;
    const int n    = blockIdx.z;

    const unsigned* xt = g_xt + (size_t)n * C_IN * T_LEN;
    const unsigned* wt = g_wt + wsel * C_IN * C_IN + o0 * C_IN;

    const unsigned xsb = su32(Xs);
    const unsigned wsb = su32(Ws);

    auto stage = [&](int buf, int c0) {
        const unsigned xdst = xsb + (unsigned)buf * (32 * 72 * 4);
        const unsigned wdst = wsb + (unsigned)buf * (64 * 36 * 4);
        #pragma unroll
        for (int l = 0; l < 4; l++) {
            int idx = l * 128 + tid;
            int cc  = idx >> 4;
            int t4  = (idx & 15) * 4;
            cp16(xdst + (unsigned)(cc * 72 + t4) * 4,
                 &xt[(size_t)(c0 + cc) * T_LEN + t0 + t4]);
        }
        #pragma unroll
        for (int l = 0; l < 4; l++) {
            int idx = l * 128 + tid;
            int o   = idx >> 3;
            int c4  = (idx & 7) * 4;
            cp16(wdst + (unsigned)(o * 36 + c4) * 4,
                 &wt[o * C_IN + c0 + c4]);
        }
    };

    stage(0, 0);
    cp_commit();

    const int ow = warp * 16;
    float C[8][4];
    #pragma unroll
    for (int j = 0; j < 8; j++)
        #pragma unroll
        for (int i = 0; i < 4; i++) C[j][i] = 0.0f;

    #pragma unroll 1
    for (int ch = 0; ch < C_IN / 32; ch++) {
        const int buf = ch & 1;
        if (ch + 1 < C_IN / 32) {
            stage(1 - buf, (ch + 1) * 32);
            cp_commit();
            cp_wait<1>();
        } else {
            cp_wait<0>();
        }
        __syncthreads();

        const unsigned* W = Ws[buf];
        const unsigned* X = Xs[buf];

        unsigned a[4][4];
        #pragma unroll
        for (int kk = 0; kk < 4; kk++) {
            a[kk][0] = W[(ow + g    ) * 36 + kk * 8 + c    ];
            a[kk][1] = W[(ow + g + 8) * 36 + kk * 8 + c    ];
            a[kk][2] = W[(ow + g    ) * 36 + kk * 8 + c + 4];
            a[kk][3] = W[(ow + g + 8) * 36 + kk * 8 + c + 4];
        }

        #pragma unroll
        for (int j = 0; j < 8; j++) {
            #pragma unroll
            for (int kk = 0; kk < 4; kk++) {
                unsigned b0 = X[(kk * 8 + c    ) * 72 + j * 8 + g];
                unsigned b1 = X[(kk * 8 + c + 4) * 72 + j * 8 + g];
                mma_tf32(C[j], a[kk], b0, b1);
            }
        }
        __syncthreads();
    }

    if (wsel < 2) {
        // Transpose 64o x 64t tile to [t][o] fp16 in smem, then write
        // coalesced rows to g_qh/g_kh [n][h][t][32].
        __half* Tr = (__half*)Xs;                 // [64 t][72 halves]
        const int lo = ow + g;
        #pragma unroll
        for (int j = 0; j < 8; j++) {
            int tl = j * 8 + 2 * c;
            Tr[(size_t)tl * 72 + lo]           = __float2half(C[j][0]);
            Tr[(size_t)(tl + 1) * 72 + lo]     = __float2half(C[j][1]);
            Tr[(size_t)tl * 72 + lo + 8]       = __float2half(C[j][2]);
            Tr[(size_t)(tl + 1) * 72 + lo + 8] = __float2half(C[j][3]);
        }
        __syncthreads();

        __half* outT = (wsel == 0 ? g_qh : g_kh);
        const int h0 = o0 >> 5;                   // CTA covers heads h0, h0+1
        #pragma unroll
        for (int l = 0; l < 4; l++) {
            int idx = l * 128 + tid;              // 0..511
            int t   = idx >> 3;
            int seg = idx & 7;                    // local-o segment of 8 halves
            int hh  = h0 + (seg >> 2);
            int d8  = (seg & 3) * 8;
            uint4 v = *(uint4*)&Tr[(size_t)t * 72 + seg * 8];
            *(uint4*)&outT[(((size_t)n * HEADS + hh) * T_LEN + t0 + t) * DK + d8] = v;
        }
    } else {
        __half* ob = g_v + (size_t)n * C_IN * T_LEN;
        const int r0 = o0 + ow + g;
        #pragma unroll
        for (int j = 0; j < 8; j++) {
            int tcol = t0 + j * 8 + 2 * c;
            *(unsigned*)&ob[(size_t)r0 * T_LEN + tcol]       = pack_h2(C[j][0], C[j][1]);
            *(unsigned*)&ob[(size_t)(r0 + 8) * T_LEN + tcol] = pack_h2(C[j][2], C[j][3]);
        }
    }
}

// ---------------------------------------------------------------------------
// Flash attention, all-fp16 MMA (m16n8k16), cp.async double-buffered.
//   Q/K tiles from transposed [t][d] global layout -> contiguous 4KB stages.
//   Qs/Ks rows: 32 halves + 8 pad = 80B (16B-aligned chunks, conflict-free
//   word-stride 20). Vs unchanged [dv][key] 144B rows.
// grid = (T/64, H, N), block = 128.
// ---------------------------------------------------------------------------
#define QT 64
#define KT 64
#define NTILES (T_LEN / KT)

__global__ __launch_bounds__(128) void attn_kernel(float* __restrict__ out)
{
    __shared__ __align__(16) __half Qs[64 * 40];        //  5120 B
    __shared__ __align__(16) __half Ks[2][64 * 40];     // 10240 B
    __shared__ __align__(16) __half Vs[2][32 * 72];     //  9216 B

    const int tid  = threadIdx.x;
    const int warp = tid >> 5;
    const int lane = tid & 31;
    const int g    = lane >> 2;
    const int c    = lane & 3;

    const int t0 = blockIdx.x * QT;
    const int h  = blockIdx.y;
    const int n  = blockIdx.z;

    const __half* qT = g_qh + (((size_t)n * HEADS + h) * T_LEN) * DK;
    const __half* kT = g_kh + (((size_t)n * HEADS + h) * T_LEN) * DK;
    const __half* vb = g_v  + (((size_t)n * HEADS + h) * DK) * T_LEN;

    const unsigned qsb = su32(Qs);
    const unsigned ksb = su32(Ks);
    const unsigned vsb = su32(Vs);

    // Stage Q tile (contiguous 4KB: 256 x 16B chunks) + tile 0 of K/V.
    #pragma unroll
    for (int l = 0; l < 2; l++) {
        int idx = l * 128 + tid;                 // 0..255
        cp16(qsb + (unsigned)((idx >> 2) * 80 + (idx & 3) * 16),
             qT + (size_t)t0 * DK + idx * 8);
    }
    #pragma unroll
    for (int l = 0; l < 2; l++) {
        int idx = l * 128 + tid;
        cp16(ksb + (unsigned)((idx >> 2) * 80 + (idx & 3) * 16),
             kT + idx * 8);
    }
    #pragma unroll
    for (int l = 0; l < 2; l++) {
        int idx = l * 128 + tid;                 // 0..255
        int dv  = idx >> 3;
        int k8  = (idx & 7) * 8;
        cp16(vsb + (unsigned)(dv * 72 + k8) * 2, &vb[(size_t)dv * T_LEN + k8]);
    }
    cp_commit();
    cp_wait<0>();
    __syncthreads();

    // Q fragments: 2 k-steps (d 0..15, 16..31) of m16n8k16 A-layout.
    const int q0 = warp * 16;
    const unsigned* Qw = (const unsigned*)Qs;
    unsigned aq[2][4];
    {
        const int r0 = (q0 + g) * 20, r1 = (q0 + g + 8) * 20;
        #pragma unroll
        for (int kk = 0; kk < 2; kk++) {
            aq[kk][0] = Qw[r0 + kk * 8 + c];
            aq[kk][1] = Qw[r1 + kk * 8 + c];
            aq[kk][2] = Qw[r0 + kk * 8 + 4 + c];
            aq[kk][3] = Qw[r1 + kk * 8 + 4 + c];
        }
    }

    float O[4][4];
    #pragma unroll
    for (int jn = 0; jn < 4; jn++)
        #pragma unroll
        for (int i = 0; i < 4; i++) O[jn][i] = 0.0f;
    float m0 = -1e30f, m1 = -1e30f, l0 = 0.0f, l1 = 0.0f;

    for (int it = 0; it < NTILES; it++) {
        const int buf = it & 1;

        if (it + 1 < NTILES) {
            const int s1 = (it + 1) * KT;
            const unsigned kdst = ksb + (unsigned)(1 - buf) * (64 * 80);
            const unsigned vdst = vsb + (unsigned)(1 - buf) * (32 * 144);
            #pragma unroll
            for (int l = 0; l < 2; l++) {
                int idx = l * 128 + tid;
                cp16(kdst + (unsigned)((idx >> 2) * 80 + (idx & 3) * 16),
                     kT + (size_t)s1 * DK + idx * 8);
            }
            #pragma unroll
            for (int l = 0; l < 2; l++) {
                int idx = l * 128 + tid;
                int dv  = idx >> 3;
                int k8  = (idx & 7) * 8;
                cp16(vdst + (unsigned)(dv * 72 + k8) * 2,
                     &vb[(size_t)dv * T_LEN + s1 + k8]);
            }
            cp_commit();
            cp_wait<1>();
        } else {
            cp_wait<0>();
        }
        __syncthreads();

        const unsigned* Kw  = (const unsigned*)Ks[buf];
        const unsigned* Vsu = (const unsigned*)Vs[buf];

        // S = Q*K^T : 8 n-blocks x 2 k-steps of m16n8k16 fp16.
        float S[8][4];
        #pragma unroll
        for (int j = 0; j < 8; j++)
            #pragma unroll
            for (int i = 0; i < 4; i++) S[j][i] = 0.0f;

        #pragma unroll
        for (int j = 0; j < 8; j++) {
            const int rb = (j * 8 + g) * 20;
            mma_f16(S[j], aq[0], Kw[rb + c],     Kw[rb + 4 + c]);
            mma_f16(S[j], aq[1], Kw[rb + 8 + c], Kw[rb + 12 + c]);
        }

        // Online softmax (log2 domain).
        float tm0 = -1e30f, tm1 = -1e30f;
        #pragma unroll
        for (int j = 0; j < 8; j++) {
            tm0 = fmaxf(tm0, fmaxf(S[j][0], S[j][1]));
            tm1 = fmaxf(tm1, fmaxf(S[j][2], S[j][3]));
        }
        tm0 = fmaxf(tm0, __shfl_xor_sync(0xffffffffu, tm0, 1));
        tm0 = fmaxf(tm0, __shfl_xor_sync(0xffffffffu, tm0, 2));
        tm1 = fmaxf(tm1, __shfl_xor_sync(0xffffffffu, tm1, 1));
        tm1 = fmaxf(tm1, __shfl_xor_sync(0xffffffffu, tm1, 2));

        float mn0 = fmaxf(m0, tm0), mn1 = fmaxf(m1, tm1);
        float a0 = ex2(m0 - mn0), a1 = ex2(m1 - mn1);
        m0 = mn0; m1 = mn1;

        float rs0 = 0.0f, rs1 = 0.0f;
        #pragma unroll
        for (int j = 0; j < 8; j++) {
            S[j][0] = ex2(S[j][0] - mn0);
            S[j][1] = ex2(S[j][1] - mn0);
            S[j][2] = ex2(S[j][2] - mn1);
            S[j][3] = ex2(S[j][3] - mn1);
            rs0 += S[j][0] + S[j][1];
            rs1 += S[j][2] + S[j][3];
        }
        rs0 += __shfl_xor_sync(0xffffffffu, rs0, 1);
        rs0 += __shfl_xor_sync(0xffffffffu, rs0, 2);
        rs1 += __shfl_xor_sync(0xffffffffu, rs1, 1);
        rs1 += __shfl_xor_sync(0xffffffffu, rs1, 2);
        l0 = l0 * a0 + rs0;
        l1 = l1 * a1 + rs1;

        #pragma unroll
        for (int jn = 0; jn < 4; jn++) {
            O[jn][0] *= a0; O[jn][1] *= a0;
            O[jn][2] *= a1; O[jn][3] *= a1;
        }

        // P -> fp16 A frags (C layout == A layout for m16n8k16).
        unsigned ap[4][4];
        #pragma unroll
        for (int jp = 0; jp < 4; jp++) {
            ap[jp][0] = pack_h2(S[2 * jp    ][0], S[2 * jp    ][1]);
            ap[jp][1] = pack_h2(S[2 * jp    ][2], S[2 * jp    ][3]);
            ap[jp][2] = pack_h2(S[2 * jp + 1][0], S[2 * jp + 1][1]);
            ap[jp][3] = pack_h2(S[2 * jp + 1][2], S[2 * jp + 1][3]);
        }

        // O += P * V : 4 dv-blocks x 4 k-steps of m16n8k16 fp16.
        #pragma unroll
        for (int jn = 0; jn < 4; jn++) {
            #pragma unroll
            for (int jp = 0; jp < 4; jp++) {
                unsigned b0 = Vsu[(8 * jn + g) * 36 + 8 * jp + c    ];
                unsigned b1 = Vsu[(8 * jn + g) * 36 + 8 * jp + c + 4];
                mma_f16(O[jn], ap[jp], b0, b1);
            }
        }

        __syncthreads();
    }

    // Normalize + coalesced writeback via smem (reuse Ks as float scratch).
    float inv0 = 1.0f / l0, inv1 = 1.0f / l1;
    float (*Os)[33] = (float(*)[33])Ks;
    #pragma unroll
    for (int jn = 0; jn < 4; jn++) {
        Os[q0 + g    ][8 * jn + 2 * c    ] = O[jn][0] * inv0;
        Os[q0 + g    ][8 * jn + 2 * c + 1] = O[jn][1] * inv0;
        Os[q0 + g + 8][8 * jn + 2 * c    ] = O[jn][2] * inv1;
        Os[q0 + g + 8][8 * jn + 2 * c + 1] = O[jn][3] * inv1;
    }
    __syncthreads();

    float* ob = out + (((size_t)n * HEADS + h) * DK) * T_LEN;
    for (int i = tid; i < QT * DK; i += 128) {
        int d = i >> 6;
        int q = i & 63;
        ob[(size_t)d * T_LEN + t0 + q] = Os[q][d];
    }
}

// ---------------------------------------------------------------------------
extern "C" void kernel_launch(void* const* d_in, const int* in_sizes, int n_in,
                              void* d_out, int out_size)
{
    const float* x  = (const float*)d_in[0];
    const float* Wq = (const float*)d_in[1];
    const float* Wk = (const float*)d_in[2];
    const float* Wv = (const float*)d_in[3];
    float* out = (float*)d_out;

    prep_kernel<<<512, 256>>>(x, Wq, Wk, Wv);

    dim3 pgrid(T_LEN / 64, 12, N_B);
    proj_tc_kernel<<<pgrid, 128>>>();

    dim3 agrid(T_LEN / QT, HEADS, N_B);
    attn_kernel<<<agrid, 128>>>(out);
}